// round 16
// baseline (speedup 1.0000x reference)
#include <cuda_runtime.h>
#include <math.h>

// ---------------------------------------------------------------------------
// Problem constants
// ---------------------------------------------------------------------------
#define Bn 16
#define Hn 32
#define En 64
#define Vn 258
#define Rn 64
#define Sn 64
#define Dn 127   // number of wavefront diagonals (r + t)

// ---------------------------------------------------------------------------
// Global scratch (static __device__, no allocation)
// ---------------------------------------------------------------------------
__device__ float g_outs_d[Bn * 3 * Dn * Rn * Hn];        // diag layout [b][c][s][r][k]
__device__ float g_comb0[(size_t)Bn * 3 * Dn * 96 * 64]; // [b][c][s][g][r]
__device__ float g_T0[3 * 258 * 96];                     // Wih0 @ emb
__device__ float g_M1[3 * 96 * 32];                      // Wih0 @ h2eW
__device__ float g_M2[2 * 96 * 32];                      // Wih0 @ adpW
__device__ float g_b0[3 * 96];                           // bih0 + Wih0@(h2eb[+adpb])
__device__ int   g_flagH[Bn * 3 * 2];                    // diag progress per (b,c,half)

// ---------------------------------------------------------------------------
// Packed f32x2 helpers
// ---------------------------------------------------------------------------
union P4 { float4 f; ulonglong2 u; };

__device__ __forceinline__ void fma2(unsigned long long& acc,
                                     unsigned long long a,
                                     unsigned long long b) {
    asm("fma.rn.f32x2 %0, %1, %2, %0;" : "+l"(acc) : "l"(a), "l"(b));
}
__device__ __forceinline__ float red2(unsigned long long acc) {
    float x, y;
    asm("mov.b64 {%0, %1}, %2;" : "=f"(x), "=f"(y) : "l"(acc));
    return x + y;
}
__device__ __forceinline__ void dot32(const float* __restrict__ w,
                                      const P4 x[8], unsigned long long& acc) {
    const ulonglong2* W = reinterpret_cast<const ulonglong2*>(w);
#pragma unroll
    for (int i = 0; i < 8; ++i) {
        ulonglong2 wv = W[i];
        fma2(acc, wv.x, x[i].u.x);
        fma2(acc, wv.y, x[i].u.y);
    }
}
__device__ __forceinline__ void load8s(const float* __restrict__ p, P4 x[8]) {
    const float4* q = reinterpret_cast<const float4*>(p);
#pragma unroll
    for (int i = 0; i < 8; ++i) x[i].f = q[i];
}
// HW tanh approximation (sm_75+): single MUFU op, max abs err ~1e-5.
__device__ __forceinline__ float tanh_ap(float x) {
    float y;
    asm("tanh.approx.f32 %0, %1;" : "=f"(y) : "f"(x));
    return y;
}
__device__ __forceinline__ float sigm(float x) {
    return fmaf(tanh_ap(0.5f * x), 0.5f, 0.5f);
}
__device__ __forceinline__ int ld_acq(const int* p) {
    int v;
    asm volatile("ld.global.acquire.gpu.s32 %0, [%1];" : "=r"(v) : "l"(p));
    return v;
}

// ---------------------------------------------------------------------------
// Pre-kernel 1: fold comb linear algebra into tables (+ zero pipeline flags)
// ---------------------------------------------------------------------------
__global__ void pre_kernel(const float* __restrict__ emb,
                           const float* __restrict__ Wih0,
                           const float* __restrict__ h2eW,
                           const float* __restrict__ h2eb,
                           const float* __restrict__ adpW,
                           const float* __restrict__ adpb,
                           const float* __restrict__ bih) {
    int idx = blockIdx.x * 256 + threadIdx.x;
    if (idx < 74304) {                       // T0[c][v][g]
        int c = idx / 24768, rem = idx % 24768;
        int v = rem / 96, g = rem % 96;
        const float* w = Wih0 + c * 6240 + g * 65;
        const float* e = emb + (size_t)(c * 258 + v) * 64;
        float s = 0.f;
        for (int j = 0; j < 64; ++j) s = fmaf(w[j], e[j], s);
        g_T0[idx] = s;
    } else if (idx < 74304 + 9216) {         // M1[c][g][j]
        int i = idx - 74304;
        int c = i / 3072, rem = i % 3072, g = rem / 32, j = rem % 32;
        const float* w = Wih0 + c * 6240 + g * 65;
        float s = 0.f;
        for (int e = 0; e < 65; ++e) s = fmaf(w[e], h2eW[c * 2080 + e * 32 + j], s);
        g_M1[i] = s;
    } else if (idx < 74304 + 9216 + 6144) {  // M2[c2][g][j]
        int i = idx - 74304 - 9216;
        int c2 = i / 3072, rem = i % 3072, g = rem / 32, j = rem % 32;
        const float* w = Wih0 + (c2 + 1) * 6240 + g * 65;
        float s = 0.f;
        for (int e = 0; e < 65; ++e) s = fmaf(w[e], adpW[c2 * 2080 + e * 32 + j], s);
        g_M2[i] = s;
    } else if (idx < 74304 + 9216 + 6144 + 288) {   // b0[c][g]
        int i = idx - 74304 - 9216 - 6144;
        int c = i / 96, g = i % 96;
        const float* w = Wih0 + c * 6240 + g * 65;
        float s = bih[c * 288 + g];
        for (int e = 0; e < 65; ++e) s = fmaf(w[e], h2eb[c * 65 + e], s);
        if (c > 0)
            for (int e = 0; e < 65; ++e) s = fmaf(w[e], adpb[(c - 1) * 65 + e], s);
        g_b0[i] = s;
    } else if (idx < 89952 + 96) {           // zero pipeline flags
        g_flagH[idx - 89952] = 0;
    }
}

// ---------------------------------------------------------------------------
// Pre-kernel 2: materialize comb0 per cell, diagonal layout [b][c][s][g][r].
// ---------------------------------------------------------------------------
__global__ void pre2_kernel(const int* __restrict__ x,
                            const float* __restrict__ Wih0,
                            const float* __restrict__ bhh) {
    __shared__ float w64s[96], bias_s[96];
    __shared__ int xs[64];
    const int s = blockIdx.x;
    const int bc = blockIdx.y;           // b*3 + c
    const int c = bc % 3;
    const int tid = threadIdx.x;
    const int lo = (s > 63) ? s - 63 : 0;
    const int hi = (s < 63) ? s : 63;
    if (tid < 96) {
        w64s[tid] = Wih0[c * 6240 + tid * 65 + 64];
        float bb = g_b0[c * 96 + tid];
        if (tid < 64) bb += bhh[c * 288 + tid];      // bhh r,z (layer 0)
        bias_s[tid] = bb;
    }
    if (tid >= 96 && tid - 96 <= hi - lo) {
        int r = lo + (tid - 96);
        xs[r] = x[(bc * 64 + r) * 64 + (s - r)];
    }
    __syncthreads();
    float* outp = g_comb0 + ((size_t)bc * Dn + s) * 6144;
    const float* t0c = g_T0 + c * 258 * 96;
    for (int idx = tid; idx < 96 * 64; idx += 256) {
        int g = idx >> 6, r = idx & 63;
        if (r < lo || r > hi) continue;
        float rf = (float)r * 0.03125f - 1.0f;
        outp[idx] = t0c[xs[r] * 96 + g] + rf * w64s[g] + bias_s[g];
    }
}

// ---------------------------------------------------------------------------
// Shared-memory layout for the RNN producer role (floats)
// ---------------------------------------------------------------------------
constexpr int OFF_M1   = 0;        // 96 x 32
constexpr int OFF_M2   = 3072;
constexpr int OFF_WHH0 = 6144;
constexpr int OFF_WIH1 = 9216;
constexpr int OFF_WHH1 = 12288;
constexpr int OFF_WIH2 = 15360;
constexpr int OFF_WHH2 = 18432;
constexpr int OFF_B    = 21504;    // 3 x 128 (layer biases; l=0 uses only nh part)
constexpr int OFF_H0   = 21888;    // 2 x (32 x 36) ping-pong
constexpr int OFF_H1   = 24192;    // 2 x (32 x 36)
constexpr int OFF_H2   = 26496;    // 2 x (33 x 36): slot 0 = boundary/zero, slot j+1 = local row j
constexpr int OFF_PC   = 28872;    // 2 x (32 x 36) prev-channel staging
constexpr int OFF_PJ   = 31176;    // 2 x (128 x 33) projection: planes r,z,ni,nh
constexpr int SM_RNN_END = 39624;

// ---------------------------------------------------------------------------
// RNN producer: half a channel (32 rows) per block; 96 blocks total.
// Warp-specialized: warps 0-7 compute; warps 8-15 move data AND precompute
// the L0 projection (M2@pc + Whh0@h0) for step s+1 during window 2.
// ---------------------------------------------------------------------------
__device__ void rnn_body(float* sm, int pid,
                         const float* __restrict__ WihR,
                         const float* __restrict__ Whh,
                         const float* __restrict__ bih,
                         const float* __restrict__ bhh) {
    const int tid = threadIdx.x;
    const int warp = tid >> 5, lane = tid & 31;
    const int bc = pid >> 1;
    const int h = pid & 1;
    const int R0 = h << 5;
    const int c = bc % 3;
    const bool haspc = (c > 0);

    // ---- stage weights (once) ----
    for (int i = tid; i < 3072; i += 512) {
        sm[OFF_M1 + i]   = g_M1[c * 3072 + i];
        sm[OFF_WHH0 + i] = Whh[c * 9216 + i];
        sm[OFF_WIH1 + i] = WihR[c * 6144 + i];
        sm[OFF_WHH1 + i] = Whh[c * 9216 + 3072 + i];
        sm[OFF_WIH2 + i] = WihR[c * 6144 + 3072 + i];
        sm[OFF_WHH2 + i] = Whh[c * 9216 + 6144 + i];
        if (haspc) sm[OFF_M2 + i] = g_M2[(c - 1) * 3072 + i];
    }
    for (int i = tid; i < 384; i += 512) {
        int l = i >> 7, o = i & 127;
        float v;
        if (o < 64)
            v = ((l == 0) ? 0.f : bih[(c * 3 + l) * 96 + o] +
                                  bhh[(c * 3 + l) * 96 + o]);
        else if (o < 96) {
            int g = 64 + (o - 64);
            v = (l == 0) ? 0.f : bih[(c * 3 + l) * 96 + g];
        } else {
            int g = 64 + (o - 96);
            v = bhh[(c * 3 + l) * 96 + g];
        }
        sm[OFF_B + i] = v;
    }
    for (int i = tid + OFF_H0; i < SM_RNN_END; i += 512) sm[i] = 0.f;

    const float* gprev = g_outs_d + (size_t)(bc - 1) * Dn * 2048;  // valid iff c>0
    float* gcur = g_outs_d + (size_t)bc * Dn * 2048;
    const float* cchan = g_comb0 + (size_t)bc * Dn * 6144;
    const int* flag_prev = &g_flagH[(bc - 1) * 2 + h];   // same half of prev channel
    const int* flag_h0 = &g_flagH[bc * 2];               // half 0 of own channel

    // prologue: PC + PJ for step 0 (diag 0 = row 0 only -> half 0)
    if (haspc && h == 0) {
        if (tid == 0) { while (ld_acq(flag_prev) < 1) {} }
    }
    __syncthreads();
    if (haspc && h == 0 && tid < 32) sm[OFF_PC + tid] = gprev[tid];
    __syncthreads();
    if (haspc && h == 0 && tid < 96) {
        // PJ[parity 0], row 0: planes r,z,ni get M2@pc (plane index == gate g)
        float ssum = 0.f;
        const float* m2 = sm + OFF_M2 + tid * 32;
        for (int e = 0; e < 32; ++e) ssum = fmaf(m2[e], sm[OFF_PC + e], ssum);
        sm[OFF_PJ + tid * 33] = ssum;
    }
    __syncthreads();

    for (int s = 0; s < Dn; ++s) {
        const int pong = s & 1, next = 1 - pong;
        const int lo = (s > 63) ? s - 63 : 0;
        const int hi = (s < 63) ? s : 63;
        const int lo_l = (lo > R0) ? lo : R0;
        const int hi_l = (hi < R0 + 31) ? hi : R0 + 31;
        const int nact = hi_l - lo_l + 1;                // may be <= 0

        const bool valid = lane < nact;
        const int r = lo_l + (valid ? lane : (nact > 0 ? nact - 1 : 0));
        const int j0 = r - R0;
        const bool cw = (warp < 8) && (nact > 0);        // compute role
        const int dtid = tid - 256;                      // data-warp linear id

        // bounds of step s+1 activity within this half (for staging/proj/zeros)
        const int lo2 = (s + 1 > 63) ? s - 62 : 0;
        const int hi2 = (s + 1 < 63) ? s + 1 : 63;
        const int c0_ = (lo2 > R0) ? lo2 : R0;
        const int c1_ = (hi2 < R0 + 31) ? hi2 : R0 + 31;

        // ---- top: boundary fetch (warp 8) for half 1 ----
        if (h == 1 && s >= 32 && s <= 95 && warp == 8) {
            if (lane == 0) { while (ld_acq(flag_h0) < s) {} }
            __syncwarp();
            sm[OFF_H2 + pong * 1188 + lane] =
                __ldcg(&gcur[((size_t)(s - 1) * 64 + 31) * 32 + lane]);
        }
        __syncthreads();   // sync1: boundary visible, prior step fully done

        // ===== window 1: L0 (M1@h2 + PJ)  ||  copy-out + PC stage + zeros ===
        if (cw) {
            const float* h2base = sm + OFF_H2 + pong * 1188 + j0 * 36;
            const float* h0base = sm + OFF_H0 + pong * 1152 + j0 * 36;
            const float* pjb = sm + OFF_PJ + pong * 4224;
            const float* cb = cchan + (size_t)s * 6144 + r;

            float c0[12];
#pragma unroll
            for (int kq = 0; kq < 4; ++kq) {
                int k = warp + kq * 8;
                c0[kq * 3 + 0] = cb[k * 64];
                c0[kq * 3 + 1] = cb[(k + 32) * 64];
                c0[kq * 3 + 2] = cb[(k + 64) * 64];
            }
            unsigned long long ar[4] = {0,0,0,0}, az[4] = {0,0,0,0};
            unsigned long long ani[4] = {0,0,0,0};
            P4 xv[8];
            load8s(h2base, xv);
#pragma unroll
            for (int kq = 0; kq < 4; ++kq) {
                int k = warp + kq * 8;
                dot32(sm + OFF_M1 + k * 32, xv, ar[kq]);
                dot32(sm + OFF_M1 + (k + 32) * 32, xv, az[kq]);
                dot32(sm + OFF_M1 + (k + 64) * 32, xv, ani[kq]);
            }
#pragma unroll
            for (int kq = 0; kq < 4; ++kq) {
                int k = warp + kq * 8;
                float vr = red2(ar[kq]) + c0[kq * 3 + 0] + pjb[k * 33 + j0];
                float vz = red2(az[kq]) + c0[kq * 3 + 1] + pjb[(32 + k) * 33 + j0];
                float vni = red2(ani[kq]) + c0[kq * 3 + 2] + pjb[(64 + k) * 33 + j0];
                float vnh = pjb[(96 + k) * 33 + j0] + sm[OFF_B + 96 + k];
                float rr = sigm(vr), zz = sigm(vz);
                float nn = tanh_ap(fmaf(rr, vnh, vni));
                float hold = h0base[k];
                float hnew = fmaf(zz, hold - nn, nn);
                if (valid) sm[OFF_H0 + next * 1152 + j0 * 36 + k] = hnew;
            }
        } else if (warp >= 8) {
            // copy-out previous step's layer-2 results (reads H2 pong)
            if (s > 0) {
                const int lop = (s - 1 > 63) ? s - 64 : 0;
                const int hip = (s - 1 < 63) ? s - 1 : 63;
                const int cl0 = (lop > R0) ? lop : R0;
                const int cl1 = (hip < R0 + 31) ? hip : R0 + 31;
                const int np = cl1 - cl0 + 1;
                for (int idx = dtid; idx < np * 32; idx += 256) {
                    int j = idx >> 5, k = idx & 31, rr = cl0 + j;
                    gcur[((size_t)(s - 1) * 64 + rr) * 32 + k] =
                        sm[OFF_H2 + pong * 1188 + (rr - R0 + 1) * 36 + k];
                }
            }
            // rolling zero: activate row s+1 (if owned) for step s+1
            if (s + 1 >= R0 && s + 1 <= R0 + 31 && dtid < 108) {
                int which = dtid / 36, kk = dtid - which * 36;
                int j = s + 1 - R0;
                if (which == 0)      sm[OFF_H0 + next * 1152 + j * 36 + kk] = 0.f;
                else if (which == 1) sm[OFF_H1 + next * 1152 + j * 36 + kk] = 0.f;
                else                 sm[OFF_H2 + next * 1188 + (j + 1) * 36 + kk] = 0.f;
            }
            // PC staging for step s+1 (writes PC next)
            if (haspc && s + 1 < Dn && c1_ >= c0_) {
                if (dtid == 0) { while (ld_acq(flag_prev) < s + 2) {} }
                asm volatile("bar.sync 1, 256;" ::: "memory");
                const int n2 = c1_ - c0_ + 1;
                for (int idx = dtid; idx < n2 * 32; idx += 256) {
                    int j = idx >> 5, k = idx & 31, rr = c0_ + j;
                    sm[OFF_PC + next * 1152 + (rr - R0) * 36 + k] =
                        gprev[((size_t)(s + 1) * 64 + rr) * 32 + k];
                }
            }
        }
        __syncthreads();   // sync2: copy-out of diag s-1 + staging complete

        // ---- publish: diags <= s-1 of this half are in g_outs_d ----
        if (tid == 0) {
            asm volatile("fence.acq_rel.gpu;" ::: "memory");
            asm volatile("st.global.release.gpu.s32 [%0], %1;"
                         :: "l"(&g_flagH[pid]), "r"(s) : "memory");
        }

        // ===== window 2: L1  ||  projection for step s+1 =====
        if (cw) {
            unsigned long long ar[4] = {0,0,0,0}, az[4] = {0,0,0,0};
            unsigned long long ani[4] = {0,0,0,0}, anh[4] = {0,0,0,0};
            P4 xv[8];
            const float* h1base = sm + OFF_H1 + pong * 1152 + j0 * 36;
            load8s(sm + OFF_H0 + next * 1152 + j0 * 36, xv);
#pragma unroll
            for (int kq = 0; kq < 4; ++kq) {
                int k = warp + kq * 8;
                dot32(sm + OFF_WIH1 + k * 32, xv, ar[kq]);
                dot32(sm + OFF_WIH1 + (k + 32) * 32, xv, az[kq]);
                dot32(sm + OFF_WIH1 + (k + 64) * 32, xv, ani[kq]);
            }
            load8s(h1base, xv);
#pragma unroll
            for (int kq = 0; kq < 4; ++kq) {
                int k = warp + kq * 8;
                dot32(sm + OFF_WHH1 + k * 32, xv, ar[kq]);
                dot32(sm + OFF_WHH1 + (k + 32) * 32, xv, az[kq]);
                dot32(sm + OFF_WHH1 + (k + 64) * 32, xv, anh[kq]);
            }
#pragma unroll
            for (int kq = 0; kq < 4; ++kq) {
                int k = warp + kq * 8;
                float vr = red2(ar[kq]) + sm[OFF_B + 128 + k];
                float vz = red2(az[kq]) + sm[OFF_B + 128 + 32 + k];
                float vni = red2(ani[kq]) + sm[OFF_B + 128 + 64 + k];
                float vnh = red2(anh[kq]) + sm[OFF_B + 128 + 96 + k];
                float rr = sigm(vr), zz = sigm(vz);
                float nn = tanh_ap(fmaf(rr, vnh, vni));
                float hold = h1base[k];
                float hnew = fmaf(zz, hold - nn, nn);
                if (valid) sm[OFF_H1 + next * 1152 + j0 * 36 + k] = hnew;
            }
        } else if (warp >= 8 && s + 1 < Dn && c1_ >= c0_) {
            // projection for step s+1: PJ = M2@pc + Whh0@h0 (4 planes)
            const int dw = warp - 8;
            const int row = R0 + lane;
            const bool v2 = (row >= c0_) && (row <= c1_);
            P4 pcv[8], h0v[8];
            if (haspc) load8s(sm + OFF_PC + next * 1152 + lane * 36, pcv);
            load8s(sm + OFF_H0 + next * 1152 + lane * 36, h0v);
            float* pj = sm + OFF_PJ + next * 4224;
#pragma unroll
            for (int kq = 0; kq < 4; ++kq) {
                int k = dw + kq * 8;
                unsigned long long pr = 0ull, pz = 0ull, pnh = 0ull, pni = 0ull;
                dot32(sm + OFF_WHH0 + k * 32, h0v, pr);
                dot32(sm + OFF_WHH0 + (k + 32) * 32, h0v, pz);
                dot32(sm + OFF_WHH0 + (k + 64) * 32, h0v, pnh);
                float fni = 0.f;
                if (haspc) {
                    dot32(sm + OFF_M2 + k * 32, pcv, pr);
                    dot32(sm + OFF_M2 + (k + 32) * 32, pcv, pz);
                    dot32(sm + OFF_M2 + (k + 64) * 32, pcv, pni);
                    fni = red2(pni);
                }
                if (v2) {
                    pj[k * 33 + lane]        = red2(pr);
                    pj[(32 + k) * 33 + lane] = red2(pz);
                    pj[(64 + k) * 33 + lane] = fni;
                    pj[(96 + k) * 33 + lane] = red2(pnh);
                }
            }
        }
        __syncthreads();   // sync3

        // ===== window 3: L2 =====
        if (cw) {
            unsigned long long ar[4] = {0,0,0,0}, az[4] = {0,0,0,0};
            unsigned long long ani[4] = {0,0,0,0}, anh[4] = {0,0,0,0};
            P4 xv[8];
            const float* h2base = sm + OFF_H2 + pong * 1188 + (j0 + 1) * 36;
            load8s(sm + OFF_H1 + next * 1152 + j0 * 36, xv);
#pragma unroll
            for (int kq = 0; kq < 4; ++kq) {
                int k = warp + kq * 8;
                dot32(sm + OFF_WIH2 + k * 32, xv, ar[kq]);
                dot32(sm + OFF_WIH2 + (k + 32) * 32, xv, az[kq]);
                dot32(sm + OFF_WIH2 + (k + 64) * 32, xv, ani[kq]);
            }
            load8s(h2base, xv);
#pragma unroll
            for (int kq = 0; kq < 4; ++kq) {
                int k = warp + kq * 8;
                dot32(sm + OFF_WHH2 + k * 32, xv, ar[kq]);
                dot32(sm + OFF_WHH2 + (k + 32) * 32, xv, az[kq]);
                dot32(sm + OFF_WHH2 + (k + 64) * 32, xv, anh[kq]);
            }
#pragma unroll
            for (int kq = 0; kq < 4; ++kq) {
                int k = warp + kq * 8;
                float vr = red2(ar[kq]) + sm[OFF_B + 256 + k];
                float vz = red2(az[kq]) + sm[OFF_B + 256 + 32 + k];
                float vni = red2(ani[kq]) + sm[OFF_B + 256 + 64 + k];
                float vnh = red2(anh[kq]) + sm[OFF_B + 256 + 96 + k];
                float rr = sigm(vr), zz = sigm(vz);
                float nn = tanh_ap(fmaf(rr, vnh, vni));
                float hold = h2base[k];
                float hnew = fmaf(zz, hold - nn, nn);
                if (valid) sm[OFF_H2 + next * 1188 + (j0 + 1) * 36 + k] = hnew;
            }
        }
        __syncthreads();   // sync4 (end of step)
    }
    // final copy-out: diag 126 = row 63 only (half 1); buffer next(126)=1
    if (h == 1 && tid < 32)
        gcur[((size_t)126 * 64 + 63) * 32 + tid] =
            sm[OFF_H2 + 1 * 1188 + 32 * 36 + tid];
    __syncthreads();
    if (tid == 0) {
        asm volatile("fence.acq_rel.gpu;" ::: "memory");
        asm volatile("st.global.release.gpu.s32 [%0], %1;"
                     :: "l"(&g_flagH[pid]), "r"(200) : "memory");
    }
}

// ---------------------------------------------------------------------------
// Logits role: transposed inputs + packed weights (unchanged).
// ---------------------------------------------------------------------------
template <int K2>
__device__ __forceinline__ void compute_logits(const float* __restrict__ Wp,
                                               const float* __restrict__ insT,
                                               const float* __restrict__ bs,
                                               float* __restrict__ outp, int tid) {
    const int warp = tid >> 5, lane = tid & 31;
    const int stream = warp >> 1;            // 0..7
    const int t = ((warp & 1) << 5) + lane;  // 0..63
    const unsigned long long* ip =
        reinterpret_cast<const unsigned long long*>(insT) + t;

    for (int q = stream; q < 33; q += 8) {   // v-octets (264 padded v)
        unsigned long long a[8] = {0ull, 0ull, 0ull, 0ull, 0ull, 0ull, 0ull, 0ull};
        const ulonglong2* wp =
            reinterpret_cast<const ulonglong2*>(Wp + q * (K2 * 16));
#pragma unroll 4
        for (int k2 = 0; k2 < K2; ++k2) {
            ulonglong2 w01 = wp[k2 * 4 + 0];
            ulonglong2 w23 = wp[k2 * 4 + 1];
            ulonglong2 w45 = wp[k2 * 4 + 2];
            ulonglong2 w67 = wp[k2 * 4 + 3];
            unsigned long long iv = ip[k2 * 64];
            fma2(a[0], w01.x, iv); fma2(a[1], w01.y, iv);
            fma2(a[2], w23.x, iv); fma2(a[3], w23.y, iv);
            fma2(a[4], w45.x, iv); fma2(a[5], w45.y, iv);
            fma2(a[6], w67.x, iv); fma2(a[7], w67.y, iv);
        }
        const int v0 = q * 8;
        float2* op = reinterpret_cast<float2*>(outp + t * Vn + v0);
        if (v0 + 8 <= Vn) {
#pragma unroll
            for (int j = 0; j < 4; ++j) {
                float2 o;
                o.x = red2(a[2 * j]) + bs[v0 + 2 * j];
                o.y = red2(a[2 * j + 1]) + bs[v0 + 2 * j + 1];
                op[j] = o;
            }
        } else {   // v0 = 256: only v 256, 257 are real
            float2 o;
            o.x = red2(a[0]) + bs[v0];
            o.y = red2(a[1]) + bs[v0 + 1];
            op[0] = o;
        }
    }
}

__device__ void logits_body(float* sm, int lid,
                            const float* __restrict__ emb,
                            const int* __restrict__ target,
                            const float* __restrict__ W0, const float* __restrict__ b0,
                            const float* __restrict__ W1, const float* __restrict__ b1,
                            const float* __restrict__ W2, const float* __restrict__ b2,
                            float* __restrict__ out) {
    const int tid = threadIdx.x;
    // lid -> (r, bb, ch): r-major so earliest-ready rows get resident blocks
    const int r = lid / 48;
    const int rem = lid - r * 48;
    const int bb = rem / 3;
    const int ch = rem - bb * 3;

    const float* W;
    const float* Bb;
    int K;
    if (ch == 0)      { W = W0; Bb = b0; K = 32; }
    else if (ch == 1) { W = W1; Bb = b1; K = 96; }
    else              { W = W2; Bb = b2; K = 160; }
    const int K2 = K >> 1;

    float* Wp = sm;                    // 264 * K floats (packed)
    float* insT = sm + 264 * K;        // 64 * K floats (transposed, float2 pairs)
    float* bs = insT + 64 * K;         // 264

    // stage packed weights + bias first (independent of RNN progress)
    for (int idx = tid; idx < 264 * K; idx += 512) {
        int v = idx / K, k = idx - v * K;
        float val = (v < Vn) ? W[v * K + k] : 0.f;
        int q = v >> 3, vl = v & 7, k2 = k >> 1, kk = k & 1;
        Wp[((q * K2 + k2) * 8 + vl) * 2 + kk] = val;
    }
    for (int idx = tid; idx < 264; idx += 512)
        bs[idx] = (idx < Vn) ? Bb[idx] : 0.f;

    // wait for RNN: row r diags r..r+63 ready when its half's flag >= r+64
    const int need = r + 64;
    const int* fp = &g_flagH[(bb * 3 + ch) * 2 + (r >> 5)];
    if (tid == 0) {
        int v = ld_acq(fp);
        while (v < need) { __nanosleep(256); v = ld_acq(fp); }
    }
    __syncthreads();   // broadcast acquire to block (leader-acquire + barrier)

    const size_t diagbase = (size_t)(bb * 3 + ch) * Dn;
    for (int idx = tid; idx < 64 * K; idx += 512) {
        int t = idx / K, k = idx - t * K;
        float val;
        if (k < 32) {
            val = __ldcg(&g_outs_d[(diagbase + (r + t)) * 2048 + r * 32 + k]);
        } else {
            int kk = k - 32;
            int chE = (kk < 64) ? 0 : 1;
            int ke = (kk < 64) ? kk : kk - 64;
            int tg = target[((bb * 3 + chE) * Rn + r) * Sn + t];
            val = emb[(size_t)(chE * Vn + tg) * En + ke];
        }
        insT[((k >> 1) * 64 + t) * 2 + (k & 1)] = val;
    }
    __syncthreads();

    const int rowbase = ((bb * 3 + ch) * Rn + r) * Sn;
    float* outp = out + (size_t)rowbase * Vn;
    if (K == 32)       compute_logits<16>(Wp, insT, bs, outp, tid);
    else if (K == 96)  compute_logits<48>(Wp, insT, bs, outp, tid);
    else               compute_logits<80>(Wp, insT, bs, outp, tid);
}

// ---------------------------------------------------------------------------
// Fused kernel: blocks 0..95 = RNN half-channel producers, 96.. = logits.
// 1 block/SM => all 96 producers resident in wave 1; flags monotonic.
// ---------------------------------------------------------------------------
__global__ __launch_bounds__(512, 1)
void fused_kernel(const float* __restrict__ WihR, const float* __restrict__ Whh,
                  const float* __restrict__ bih, const float* __restrict__ bhh,
                  const float* __restrict__ emb, const int* __restrict__ target,
                  const float* __restrict__ W0, const float* __restrict__ b0,
                  const float* __restrict__ W1, const float* __restrict__ b1,
                  const float* __restrict__ W2, const float* __restrict__ b2,
                  float* __restrict__ out) {
    extern __shared__ float sm[];
    if (blockIdx.x < Bn * 3 * 2) {
        rnn_body(sm, blockIdx.x, WihR, Whh, bih, bhh);
    } else {
        logits_body(sm, blockIdx.x - Bn * 3 * 2, emb, target, W0, b0, W1, b1,
                    W2, b2, out);
    }
}

// ---------------------------------------------------------------------------
// Launch
// ---------------------------------------------------------------------------
extern "C" void kernel_launch(void* const* d_in, const int* in_sizes, int n_in,
                              void* d_out, int out_size) {
    (void)in_sizes; (void)n_in; (void)out_size;
    const int*   x      = (const int*)  d_in[0];
    const int*   target = (const int*)  d_in[1];
    const float* emb    = (const float*)d_in[2];
    const float* Wih0   = (const float*)d_in[3];
    const float* WihR   = (const float*)d_in[4];
    const float* Whh    = (const float*)d_in[5];
    const float* bih    = (const float*)d_in[6];
    const float* bhh    = (const float*)d_in[7];
    const float* h2eW   = (const float*)d_in[8];
    const float* h2eb   = (const float*)d_in[9];
    const float* adpW   = (const float*)d_in[10];
    const float* adpb   = (const float*)d_in[11];
    const float* redW   = (const float*)d_in[12];
    const float* redb   = (const float*)d_in[13];
    const float* greenW = (const float*)d_in[14];
    const float* greenb = (const float*)d_in[15];
    const float* blueW  = (const float*)d_in[16];
    const float* blueb  = (const float*)d_in[17];
    float* out = (float*)d_out;

    // logits role needs the most smem: (264 + 64) * 160 + 264 floats = 210,976 B
    const size_t smem_fused = (size_t)(264 * 160 + 64 * 160 + 264) * sizeof(float);

    cudaFuncSetAttribute(fused_kernel, cudaFuncAttributeMaxDynamicSharedMemorySize,
                         (int)smem_fused);

    pre_kernel<<<352, 256>>>(emb, Wih0, h2eW, h2eb, adpW, adpb, bih);
    pre2_kernel<<<dim3(Dn, Bn * 3), 256>>>(x, Wih0, bhh);
    fused_kernel<<<Bn * 3 * 2 + Bn * Rn * 3, 512, smem_fused>>>(
        WihR, Whh, bih, bhh, emb, target, redW, redb, greenW, greenb,
        blueW, blueb, out);
}

// round 17
// speedup vs baseline: 1.0782x; 1.0782x over previous
#include <cuda_runtime.h>
#include <math.h>

// ---------------------------------------------------------------------------
// Problem constants
// ---------------------------------------------------------------------------
#define Bn 16
#define Hn 32
#define En 64
#define Vn 258
#define Rn 64
#define Sn 64
#define Dn 127   // number of wavefront diagonals (r + t)

// ---------------------------------------------------------------------------
// Global scratch (static __device__, no allocation)
// ---------------------------------------------------------------------------
__device__ float g_outs_d[Bn * 3 * Dn * Rn * Hn];        // diag layout [b][c][s][r][k]
__device__ float g_comb0[(size_t)Bn * 3 * Dn * 96 * 64]; // [b][c][s][g][r]
__device__ float g_T0[3 * 258 * 96];                     // Wih0 @ emb
__device__ float g_M1[3 * 96 * 32];                      // Wih0 @ h2eW
__device__ float g_M2[2 * 96 * 32];                      // Wih0 @ adpW
__device__ float g_b0[3 * 96];                           // bih0 + Wih0@(h2eb[+adpb])
__device__ int   g_flagH[Bn * 3 * 2];                    // diag progress per (b,c,half)

// ---------------------------------------------------------------------------
// Packed f32x2 helpers
// ---------------------------------------------------------------------------
union P4 { float4 f; ulonglong2 u; };

__device__ __forceinline__ void fma2(unsigned long long& acc,
                                     unsigned long long a,
                                     unsigned long long b) {
    asm("fma.rn.f32x2 %0, %1, %2, %0;" : "+l"(acc) : "l"(a), "l"(b));
}
__device__ __forceinline__ float red2(unsigned long long acc) {
    float x, y;
    asm("mov.b64 {%0, %1}, %2;" : "=f"(x), "=f"(y) : "l"(acc));
    return x + y;
}
__device__ __forceinline__ void dot32(const float* __restrict__ w,
                                      const P4 x[8], unsigned long long& acc) {
    const ulonglong2* W = reinterpret_cast<const ulonglong2*>(w);
#pragma unroll
    for (int i = 0; i < 8; ++i) {
        ulonglong2 wv = W[i];
        fma2(acc, wv.x, x[i].u.x);
        fma2(acc, wv.y, x[i].u.y);
    }
}
__device__ __forceinline__ void load8s(const float* __restrict__ p, P4 x[8]) {
    const float4* q = reinterpret_cast<const float4*>(p);
#pragma unroll
    for (int i = 0; i < 8; ++i) x[i].f = q[i];
}
// HW tanh approximation (sm_75+): single MUFU op, max abs err ~1e-5.
__device__ __forceinline__ float tanh_ap(float x) {
    float y;
    asm("tanh.approx.f32 %0, %1;" : "=f"(y) : "f"(x));
    return y;
}
__device__ __forceinline__ float sigm(float x) {
    return fmaf(tanh_ap(0.5f * x), 0.5f, 0.5f);
}
__device__ __forceinline__ int ld_acq(const int* p) {
    int v;
    asm volatile("ld.global.acquire.gpu.s32 %0, [%1];" : "=r"(v) : "l"(p));
    return v;
}

// ---------------------------------------------------------------------------
// Pre-kernel 1: fold comb linear algebra into tables (+ zero pipeline flags)
// ---------------------------------------------------------------------------
__global__ void pre_kernel(const float* __restrict__ emb,
                           const float* __restrict__ Wih0,
                           const float* __restrict__ h2eW,
                           const float* __restrict__ h2eb,
                           const float* __restrict__ adpW,
                           const float* __restrict__ adpb,
                           const float* __restrict__ bih) {
    int idx = blockIdx.x * 256 + threadIdx.x;
    if (idx < 74304) {                       // T0[c][v][g]
        int c = idx / 24768, rem = idx % 24768;
        int v = rem / 96, g = rem % 96;
        const float* w = Wih0 + c * 6240 + g * 65;
        const float* e = emb + (size_t)(c * 258 + v) * 64;
        float s = 0.f;
        for (int j = 0; j < 64; ++j) s = fmaf(w[j], e[j], s);
        g_T0[idx] = s;
    } else if (idx < 74304 + 9216) {         // M1[c][g][j]
        int i = idx - 74304;
        int c = i / 3072, rem = i % 3072, g = rem / 32, j = rem % 32;
        const float* w = Wih0 + c * 6240 + g * 65;
        float s = 0.f;
        for (int e = 0; e < 65; ++e) s = fmaf(w[e], h2eW[c * 2080 + e * 32 + j], s);
        g_M1[i] = s;
    } else if (idx < 74304 + 9216 + 6144) {  // M2[c2][g][j]
        int i = idx - 74304 - 9216;
        int c2 = i / 3072, rem = i % 3072, g = rem / 32, j = rem % 32;
        const float* w = Wih0 + (c2 + 1) * 6240 + g * 65;
        float s = 0.f;
        for (int e = 0; e < 65; ++e) s = fmaf(w[e], adpW[c2 * 2080 + e * 32 + j], s);
        g_M2[i] = s;
    } else if (idx < 74304 + 9216 + 6144 + 288) {   // b0[c][g]
        int i = idx - 74304 - 9216 - 6144;
        int c = i / 96, g = i % 96;
        const float* w = Wih0 + c * 6240 + g * 65;
        float s = bih[c * 288 + g];
        for (int e = 0; e < 65; ++e) s = fmaf(w[e], h2eb[c * 65 + e], s);
        if (c > 0)
            for (int e = 0; e < 65; ++e) s = fmaf(w[e], adpb[(c - 1) * 65 + e], s);
        g_b0[i] = s;
    } else if (idx < 89952 + 96) {           // zero pipeline flags
        g_flagH[idx - 89952] = 0;
    }
}

// ---------------------------------------------------------------------------
// Pre-kernel 2: materialize comb0 per cell, diagonal layout [b][c][s][g][r].
// ---------------------------------------------------------------------------
__global__ void pre2_kernel(const int* __restrict__ x,
                            const float* __restrict__ Wih0,
                            const float* __restrict__ bhh) {
    __shared__ float w64s[96], bias_s[96];
    __shared__ int xs[64];
    const int s = blockIdx.x;
    const int bc = blockIdx.y;           // b*3 + c
    const int c = bc % 3;
    const int tid = threadIdx.x;
    const int lo = (s > 63) ? s - 63 : 0;
    const int hi = (s < 63) ? s : 63;
    if (tid < 96) {
        w64s[tid] = Wih0[c * 6240 + tid * 65 + 64];
        float bb = g_b0[c * 96 + tid];
        if (tid < 64) bb += bhh[c * 288 + tid];      // bhh r,z (layer 0)
        bias_s[tid] = bb;
    }
    if (tid >= 96 && tid - 96 <= hi - lo) {
        int r = lo + (tid - 96);
        xs[r] = x[(bc * 64 + r) * 64 + (s - r)];
    }
    __syncthreads();
    float* outp = g_comb0 + ((size_t)bc * Dn + s) * 6144;
    const float* t0c = g_T0 + c * 258 * 96;
    for (int idx = tid; idx < 96 * 64; idx += 256) {
        int g = idx >> 6, r = idx & 63;
        if (r < lo || r > hi) continue;
        float rf = (float)r * 0.03125f - 1.0f;
        outp[idx] = t0c[xs[r] * 96 + g] + rf * w64s[g] + bias_s[g];
    }
}

// ---------------------------------------------------------------------------
// Shared-memory layout for the RNN producer role (floats)
// ---------------------------------------------------------------------------
constexpr int OFF_M1   = 0;        // 96 x 32
constexpr int OFF_M2   = 3072;
constexpr int OFF_WHH0 = 6144;
constexpr int OFF_WIH1 = 9216;
constexpr int OFF_WHH1 = 12288;
constexpr int OFF_WIH2 = 15360;
constexpr int OFF_WHH2 = 18432;
constexpr int OFF_B    = 21504;    // 3 x 128 (layer biases; l=0 uses only nh part)
constexpr int OFF_H0   = 21888;    // 2 x (32 x 36) ping-pong
constexpr int OFF_H1   = 24192;    // 2 x (32 x 36)
constexpr int OFF_H2   = 26496;    // 2 x (33 x 36): slot 0 = boundary/zero, slot j+1 = local row j
constexpr int OFF_PC   = 28872;    // 2 x (32 x 36) prev-channel staging
constexpr int SM_RNN_END = 31176;

// ---------------------------------------------------------------------------
// RNN producer: half a channel (32 rows) per block; 96 blocks total.
// Warp-specialized: warps 0-7 compute (4 k-units each, 16 packed accs);
// warps 8-15 move data. Boundary vector for half 1 is PREFETCHED one step
// ahead (window 2, warp 12) so no serial fetch sits at the top of a step.
// 3 block barriers per step.
// ---------------------------------------------------------------------------
__device__ void rnn_body(float* sm, int pid,
                         const float* __restrict__ WihR,
                         const float* __restrict__ Whh,
                         const float* __restrict__ bih,
                         const float* __restrict__ bhh) {
    const int tid = threadIdx.x;
    const int warp = tid >> 5, lane = tid & 31;
    const int bc = pid >> 1;
    const int h = pid & 1;
    const int R0 = h << 5;
    const int c = bc % 3;
    const bool haspc = (c > 0);

    // ---- stage weights (once) ----
    for (int i = tid; i < 3072; i += 512) {
        sm[OFF_M1 + i]   = g_M1[c * 3072 + i];
        sm[OFF_WHH0 + i] = Whh[c * 9216 + i];
        sm[OFF_WIH1 + i] = WihR[c * 6144 + i];
        sm[OFF_WHH1 + i] = Whh[c * 9216 + 3072 + i];
        sm[OFF_WIH2 + i] = WihR[c * 6144 + 3072 + i];
        sm[OFF_WHH2 + i] = Whh[c * 9216 + 6144 + i];
        if (haspc) sm[OFF_M2 + i] = g_M2[(c - 1) * 3072 + i];
    }
    for (int i = tid; i < 384; i += 512) {
        int l = i >> 7, o = i & 127;
        float v;
        if (o < 64)
            v = ((l == 0) ? 0.f : bih[(c * 3 + l) * 96 + o] +
                                  bhh[(c * 3 + l) * 96 + o]);
        else if (o < 96) {
            int g = 64 + (o - 64);
            v = (l == 0) ? 0.f : bih[(c * 3 + l) * 96 + g];
        } else {
            int g = 64 + (o - 96);
            v = bhh[(c * 3 + l) * 96 + g];
        }
        sm[OFF_B + i] = v;
    }
    for (int i = tid + OFF_H0; i < SM_RNN_END; i += 512) sm[i] = 0.f;

    const float* gprev = g_outs_d + (size_t)(bc - 1) * Dn * 2048;  // valid iff c>0
    float* gcur = g_outs_d + (size_t)bc * Dn * 2048;
    const float* cchan = g_comb0 + (size_t)bc * Dn * 6144;
    const int* flag_prev = &g_flagH[(bc - 1) * 2 + h];   // same half of prev channel
    const int* flag_h0 = &g_flagH[bc * 2];               // half 0 of own channel

    // prologue: PC for step 0 (diag 0 = row 0 only -> half 0)
    if (haspc && h == 0) {
        if (tid == 0) { while (ld_acq(flag_prev) < 1) {} }
    }
    __syncthreads();
    if (haspc && h == 0 && tid < 32) sm[OFF_PC + tid] = gprev[tid];
    __syncthreads();

    for (int s = 0; s < Dn; ++s) {
        const int pong = s & 1, next = 1 - pong;
        const int lo = (s > 63) ? s - 63 : 0;
        const int hi = (s < 63) ? s : 63;
        const int lo_l = (lo > R0) ? lo : R0;
        const int hi_l = (hi < R0 + 31) ? hi : R0 + 31;
        const int nact = hi_l - lo_l + 1;                // may be <= 0

        const bool valid = lane < nact;
        const int r = lo_l + (valid ? lane : (nact > 0 ? nact - 1 : 0));
        const int j0 = r - R0;
        const bool cw = (warp < 8) && (nact > 0);        // compute role
        const int dtid = tid - 256;                      // data-warp linear id

        // ===== window 1: L0  ||  copy-out + PC stage =====
        // (boundary vector at H2 pong slot 0 was prefetched in window 2 of
        //  step s-1; ordered by sync3 of step s-1)
        if (cw) {
            const float* h2base = sm + OFF_H2 + pong * 1188 + j0 * 36;
            const float* h0base = sm + OFF_H0 + pong * 1152 + j0 * 36;
            const float* pcbase = sm + OFF_PC + pong * 1152 + j0 * 36;
            const float* cb = cchan + (size_t)s * 6144 + r;

            float c0[12];
#pragma unroll
            for (int kq = 0; kq < 4; ++kq) {
                int k = warp + kq * 8;
                c0[kq * 3 + 0] = cb[k * 64];
                c0[kq * 3 + 1] = cb[(k + 32) * 64];
                c0[kq * 3 + 2] = cb[(k + 64) * 64];
            }
            unsigned long long ar[4] = {0,0,0,0}, az[4] = {0,0,0,0};
            unsigned long long ani[4] = {0,0,0,0}, anh[4] = {0,0,0,0};
            P4 xv[8];
            load8s(h2base, xv);
#pragma unroll
            for (int kq = 0; kq < 4; ++kq) {
                int k = warp + kq * 8;
                dot32(sm + OFF_M1 + k * 32, xv, ar[kq]);
                dot32(sm + OFF_M1 + (k + 32) * 32, xv, az[kq]);
                dot32(sm + OFF_M1 + (k + 64) * 32, xv, ani[kq]);
            }
            if (haspc) {
                load8s(pcbase, xv);
#pragma unroll
                for (int kq = 0; kq < 4; ++kq) {
                    int k = warp + kq * 8;
                    dot32(sm + OFF_M2 + k * 32, xv, ar[kq]);
                    dot32(sm + OFF_M2 + (k + 32) * 32, xv, az[kq]);
                    dot32(sm + OFF_M2 + (k + 64) * 32, xv, ani[kq]);
                }
            }
            load8s(h0base, xv);
#pragma unroll
            for (int kq = 0; kq < 4; ++kq) {
                int k = warp + kq * 8;
                dot32(sm + OFF_WHH0 + k * 32, xv, ar[kq]);
                dot32(sm + OFF_WHH0 + (k + 32) * 32, xv, az[kq]);
                dot32(sm + OFF_WHH0 + (k + 64) * 32, xv, anh[kq]);
            }
#pragma unroll
            for (int kq = 0; kq < 4; ++kq) {
                int k = warp + kq * 8;
                float vr = red2(ar[kq]) + c0[kq * 3 + 0];
                float vz = red2(az[kq]) + c0[kq * 3 + 1];
                float vni = red2(ani[kq]) + c0[kq * 3 + 2];
                float vnh = red2(anh[kq]) + sm[OFF_B + 96 + k];
                float rr = sigm(vr), zz = sigm(vz);
                float nn = tanh_ap(fmaf(rr, vnh, vni));
                float hold = h0base[k];
                float hnew = fmaf(zz, hold - nn, nn);
                if (valid) sm[OFF_H0 + next * 1152 + j0 * 36 + k] = hnew;
            }
        } else if (warp >= 8) {
            // copy-out previous step's layer-2 results (reads H2 pong)
            if (s > 0) {
                const int lop = (s - 1 > 63) ? s - 64 : 0;
                const int hip = (s - 1 < 63) ? s - 1 : 63;
                const int cl0 = (lop > R0) ? lop : R0;
                const int cl1 = (hip < R0 + 31) ? hip : R0 + 31;
                const int np = cl1 - cl0 + 1;
                for (int idx = dtid; idx < np * 32; idx += 256) {
                    int j = idx >> 5, k = idx & 31, rr = cl0 + j;
                    gcur[((size_t)(s - 1) * 64 + rr) * 32 + k] =
                        sm[OFF_H2 + pong * 1188 + (rr - R0 + 1) * 36 + k];
                }
            }
            // PC staging for step s+1 (writes PC next)
            if (haspc && s + 1 < Dn) {
                const int lo2 = (s + 1 > 63) ? s - 62 : 0;
                const int hi2 = (s + 1 < 63) ? s + 1 : 63;
                const int c0_ = (lo2 > R0) ? lo2 : R0;
                const int c1_ = (hi2 < R0 + 31) ? hi2 : R0 + 31;
                const int n2 = c1_ - c0_ + 1;
                if (n2 > 0) {
                    if (dtid == 0) { while (ld_acq(flag_prev) < s + 2) {} }
                    asm volatile("bar.sync 1, 256;" ::: "memory");
                    for (int idx = dtid; idx < n2 * 32; idx += 256) {
                        int j = idx >> 5, k = idx & 31, rr = c0_ + j;
                        sm[OFF_PC + next * 1152 + (rr - R0) * 36 + k] =
                            gprev[((size_t)(s + 1) * 64 + rr) * 32 + k];
                    }
                }
            }
        }
        __syncthreads();   // sync1: copy-out of diag s-1 complete

        // ---- publish: diags <= s-1 of this half are in g_outs_d ----
        if (tid == 0) {
            asm volatile("fence.acq_rel.gpu;" ::: "memory");
            asm volatile("st.global.release.gpu.s32 [%0], %1;"
                         :: "l"(&g_flagH[pid]), "r"(s) : "memory");
        }

        // ===== window 2: L1  ||  boundary prefetch for step s+1 =====
        if (cw) {
            unsigned long long ar[4] = {0,0,0,0}, az[4] = {0,0,0,0};
            unsigned long long ani[4] = {0,0,0,0}, anh[4] = {0,0,0,0};
            P4 xv[8];
            const float* h1base = sm + OFF_H1 + pong * 1152 + j0 * 36;
            load8s(sm + OFF_H0 + next * 1152 + j0 * 36, xv);
#pragma unroll
            for (int kq = 0; kq < 4; ++kq) {
                int k = warp + kq * 8;
                dot32(sm + OFF_WIH1 + k * 32, xv, ar[kq]);
                dot32(sm + OFF_WIH1 + (k + 32) * 32, xv, az[kq]);
                dot32(sm + OFF_WIH1 + (k + 64) * 32, xv, ani[kq]);
            }
            load8s(h1base, xv);
#pragma unroll
            for (int kq = 0; kq < 4; ++kq) {
                int k = warp + kq * 8;
                dot32(sm + OFF_WHH1 + k * 32, xv, ar[kq]);
                dot32(sm + OFF_WHH1 + (k + 32) * 32, xv, az[kq]);
                dot32(sm + OFF_WHH1 + (k + 64) * 32, xv, anh[kq]);
            }
#pragma unroll
            for (int kq = 0; kq < 4; ++kq) {
                int k = warp + kq * 8;
                float vr = red2(ar[kq]) + sm[OFF_B + 128 + k];
                float vz = red2(az[kq]) + sm[OFF_B + 128 + 32 + k];
                float vni = red2(ani[kq]) + sm[OFF_B + 128 + 64 + k];
                float vnh = red2(anh[kq]) + sm[OFF_B + 128 + 96 + k];
                float rr = sigm(vr), zz = sigm(vz);
                float nn = tanh_ap(fmaf(rr, vnh, vni));
                float hold = h1base[k];
                float hnew = fmaf(zz, hold - nn, nn);
                if (valid) sm[OFF_H1 + next * 1152 + j0 * 36 + k] = hnew;
            }
        } else if (h == 1 && warp == 12 && s + 1 >= 32 && s + 1 <= 95) {
            // prefetch half 0's row-31 output of diag s into H2 next slot 0
            // (read by window 1 of step s+1 as the boundary vector)
            if (lane == 0) { while (ld_acq(flag_h0) < s + 1) {} }
            __syncwarp();
            sm[OFF_H2 + next * 1188 + lane] =
                __ldcg(&gcur[((size_t)s * 64 + 31) * 32 + lane]);
        }
        __syncthreads();   // sync2

        // ===== window 3: L2  ||  rolling zeros =====
        if (cw) {
            unsigned long long ar[4] = {0,0,0,0}, az[4] = {0,0,0,0};
            unsigned long long ani[4] = {0,0,0,0}, anh[4] = {0,0,0,0};
            P4 xv[8];
            const float* h2base = sm + OFF_H2 + pong * 1188 + (j0 + 1) * 36;
            load8s(sm + OFF_H1 + next * 1152 + j0 * 36, xv);
#pragma unroll
            for (int kq = 0; kq < 4; ++kq) {
                int k = warp + kq * 8;
                dot32(sm + OFF_WIH2 + k * 32, xv, ar[kq]);
                dot32(sm + OFF_WIH2 + (k + 32) * 32, xv, az[kq]);
                dot32(sm + OFF_WIH2 + (k + 64) * 32, xv, ani[kq]);
            }
            load8s(h2base, xv);
#pragma unroll
            for (int kq = 0; kq < 4; ++kq) {
                int k = warp + kq * 8;
                dot32(sm + OFF_WHH2 + k * 32, xv, ar[kq]);
                dot32(sm + OFF_WHH2 + (k + 32) * 32, xv, az[kq]);
                dot32(sm + OFF_WHH2 + (k + 64) * 32, xv, anh[kq]);
            }
#pragma unroll
            for (int kq = 0; kq < 4; ++kq) {
                int k = warp + kq * 8;
                float vr = red2(ar[kq]) + sm[OFF_B + 256 + k];
                float vz = red2(az[kq]) + sm[OFF_B + 256 + 32 + k];
                float vni = red2(ani[kq]) + sm[OFF_B + 256 + 64 + k];
                float vnh = red2(anh[kq]) + sm[OFF_B + 256 + 96 + k];
                float rr = sigm(vr), zz = sigm(vz);
                float nn = tanh_ap(fmaf(rr, vnh, vni));
                float hold = h2base[k];
                float hnew = fmaf(zz, hold - nn, nn);
                if (valid) sm[OFF_H2 + next * 1188 + (j0 + 1) * 36 + k] = hnew;
            }
        } else if (warp >= 8) {
            // rolling zero: activate row s+1 (if owned) for step s+1
            if (s + 1 >= R0 && s + 1 <= R0 + 31 && dtid < 108) {
                int which = dtid / 36, kk = dtid - which * 36;
                int j = s + 1 - R0;
                if (which == 0)      sm[OFF_H0 + next * 1152 + j * 36 + kk] = 0.f;
                else if (which == 1) sm[OFF_H1 + next * 1152 + j * 36 + kk] = 0.f;
                else                 sm[OFF_H2 + next * 1188 + (j + 1) * 36 + kk] = 0.f;
            }
        }
        __syncthreads();   // sync3 (end of step)
    }
    // final copy-out: diag 126 = row 63 only (half 1); buffer next(126)=1
    if (h == 1 && tid < 32)
        gcur[((size_t)126 * 64 + 63) * 32 + tid] =
            sm[OFF_H2 + 1 * 1188 + 32 * 36 + tid];
    __syncthreads();
    if (tid == 0) {
        asm volatile("fence.acq_rel.gpu;" ::: "memory");
        asm volatile("st.global.release.gpu.s32 [%0], %1;"
                     :: "l"(&g_flagH[pid]), "r"(200) : "memory");
    }
}

// ---------------------------------------------------------------------------
// Logits role: transposed inputs + packed weights (unchanged).
// ---------------------------------------------------------------------------
template <int K2>
__device__ __forceinline__ void compute_logits(const float* __restrict__ Wp,
                                               const float* __restrict__ insT,
                                               const float* __restrict__ bs,
                                               float* __restrict__ outp, int tid) {
    const int warp = tid >> 5, lane = tid & 31;
    const int stream = warp >> 1;            // 0..7
    const int t = ((warp & 1) << 5) + lane;  // 0..63
    const unsigned long long* ip =
        reinterpret_cast<const unsigned long long*>(insT) + t;

    for (int q = stream; q < 33; q += 8) {   // v-octets (264 padded v)
        unsigned long long a[8] = {0ull, 0ull, 0ull, 0ull, 0ull, 0ull, 0ull, 0ull};
        const ulonglong2* wp =
            reinterpret_cast<const ulonglong2*>(Wp + q * (K2 * 16));
#pragma unroll 4
        for (int k2 = 0; k2 < K2; ++k2) {
            ulonglong2 w01 = wp[k2 * 4 + 0];
            ulonglong2 w23 = wp[k2 * 4 + 1];
            ulonglong2 w45 = wp[k2 * 4 + 2];
            ulonglong2 w67 = wp[k2 * 4 + 3];
            unsigned long long iv = ip[k2 * 64];
            fma2(a[0], w01.x, iv); fma2(a[1], w01.y, iv);
            fma2(a[2], w23.x, iv); fma2(a[3], w23.y, iv);
            fma2(a[4], w45.x, iv); fma2(a[5], w45.y, iv);
            fma2(a[6], w67.x, iv); fma2(a[7], w67.y, iv);
        }
        const int v0 = q * 8;
        float2* op = reinterpret_cast<float2*>(outp + t * Vn + v0);
        if (v0 + 8 <= Vn) {
#pragma unroll
            for (int j = 0; j < 4; ++j) {
                float2 o;
                o.x = red2(a[2 * j]) + bs[v0 + 2 * j];
                o.y = red2(a[2 * j + 1]) + bs[v0 + 2 * j + 1];
                op[j] = o;
            }
        } else {   // v0 = 256: only v 256, 257 are real
            float2 o;
            o.x = red2(a[0]) + bs[v0];
            o.y = red2(a[1]) + bs[v0 + 1];
            op[0] = o;
        }
    }
}

__device__ void logits_body(float* sm, int lid,
                            const float* __restrict__ emb,
                            const int* __restrict__ target,
                            const float* __restrict__ W0, const float* __restrict__ b0,
                            const float* __restrict__ W1, const float* __restrict__ b1,
                            const float* __restrict__ W2, const float* __restrict__ b2,
                            float* __restrict__ out) {
    const int tid = threadIdx.x;
    // lid -> (r, bb, ch): r-major so earliest-ready rows get resident blocks
    const int r = lid / 48;
    const int rem = lid - r * 48;
    const int bb = rem / 3;
    const int ch = rem - bb * 3;

    const float* W;
    const float* Bb;
    int K;
    if (ch == 0)      { W = W0; Bb = b0; K = 32; }
    else if (ch == 1) { W = W1; Bb = b1; K = 96; }
    else              { W = W2; Bb = b2; K = 160; }
    const int K2 = K >> 1;

    float* Wp = sm;                    // 264 * K floats (packed)
    float* insT = sm + 264 * K;        // 64 * K floats (transposed, float2 pairs)
    float* bs = insT + 64 * K;         // 264

    // stage packed weights + bias first (independent of RNN progress)
    for (int idx = tid; idx < 264 * K; idx += 512) {
        int v = idx / K, k = idx - v * K;
        float val = (v < Vn) ? W[v * K + k] : 0.f;
        int q = v >> 3, vl = v & 7, k2 = k >> 1, kk = k & 1;
        Wp[((q * K2 + k2) * 8 + vl) * 2 + kk] = val;
    }
    for (int idx = tid; idx < 264; idx += 512)
        bs[idx] = (idx < Vn) ? Bb[idx] : 0.f;

    // wait for RNN: row r diags r..r+63 ready when its half's flag >= r+64
    const int need = r + 64;
    const int* fp = &g_flagH[(bb * 3 + ch) * 2 + (r >> 5)];
    if (tid == 0) {
        int v = ld_acq(fp);
        while (v < need) { __nanosleep(256); v = ld_acq(fp); }
    }
    __syncthreads();   // broadcast acquire to block (leader-acquire + barrier)

    const size_t diagbase = (size_t)(bb * 3 + ch) * Dn;
    for (int idx = tid; idx < 64 * K; idx += 512) {
        int t = idx / K, k = idx - t * K;
        float val;
        if (k < 32) {
            val = __ldcg(&g_outs_d[(diagbase + (r + t)) * 2048 + r * 32 + k]);
        } else {
            int kk = k - 32;
            int chE = (kk < 64) ? 0 : 1;
            int ke = (kk < 64) ? kk : kk - 64;
            int tg = target[((bb * 3 + chE) * Rn + r) * Sn + t];
            val = emb[(size_t)(chE * Vn + tg) * En + ke];
        }
        insT[((k >> 1) * 64 + t) * 2 + (k & 1)] = val;
    }
    __syncthreads();

    const int rowbase = ((bb * 3 + ch) * Rn + r) * Sn;
    float* outp = out + (size_t)rowbase * Vn;
    if (K == 32)       compute_logits<16>(Wp, insT, bs, outp, tid);
    else if (K == 96)  compute_logits<48>(Wp, insT, bs, outp, tid);
    else               compute_logits<80>(Wp, insT, bs, outp, tid);
}

// ---------------------------------------------------------------------------
// Fused kernel: blocks 0..95 = RNN half-channel producers, 96.. = logits.
// 1 block/SM => all 96 producers resident in wave 1; flags monotonic.
// ---------------------------------------------------------------------------
__global__ __launch_bounds__(512, 1)
void fused_kernel(const float* __restrict__ WihR, const float* __restrict__ Whh,
                  const float* __restrict__ bih, const float* __restrict__ bhh,
                  const float* __restrict__ emb, const int* __restrict__ target,
                  const float* __restrict__ W0, const float* __restrict__ b0,
                  const float* __restrict__ W1, const float* __restrict__ b1,
                  const float* __restrict__ W2, const float* __restrict__ b2,
                  float* __restrict__ out) {
    extern __shared__ float sm[];
    if (blockIdx.x < Bn * 3 * 2) {
        rnn_body(sm, blockIdx.x, WihR, Whh, bih, bhh);
    } else {
        logits_body(sm, blockIdx.x - Bn * 3 * 2, emb, target, W0, b0, W1, b1,
                    W2, b2, out);
    }
}

// ---------------------------------------------------------------------------
// Launch
// ---------------------------------------------------------------------------
extern "C" void kernel_launch(void* const* d_in, const int* in_sizes, int n_in,
                              void* d_out, int out_size) {
    (void)in_sizes; (void)n_in; (void)out_size;
    const int*   x      = (const int*)  d_in[0];
    const int*   target = (const int*)  d_in[1];
    const float* emb    = (const float*)d_in[2];
    const float* Wih0   = (const float*)d_in[3];
    const float* WihR   = (const float*)d_in[4];
    const float* Whh    = (const float*)d_in[5];
    const float* bih    = (const float*)d_in[6];
    const float* bhh    = (const float*)d_in[7];
    const float* h2eW   = (const float*)d_in[8];
    const float* h2eb   = (const float*)d_in[9];
    const float* adpW   = (const float*)d_in[10];
    const float* adpb   = (const float*)d_in[11];
    const float* redW   = (const float*)d_in[12];
    const float* redb   = (const float*)d_in[13];
    const float* greenW = (const float*)d_in[14];
    const float* greenb = (const float*)d_in[15];
    const float* blueW  = (const float*)d_in[16];
    const float* blueb  = (const float*)d_in[17];
    float* out = (float*)d_out;

    // logits role needs the most smem: (264 + 64) * 160 + 264 floats = 210,976 B
    const size_t smem_fused = (size_t)(264 * 160 + 64 * 160 + 264) * sizeof(float);

    cudaFuncSetAttribute(fused_kernel, cudaFuncAttributeMaxDynamicSharedMemorySize,
                         (int)smem_fused);

    pre_kernel<<<352, 256>>>(emb, Wih0, h2eW, h2eb, adpW, adpb, bih);
    pre2_kernel<<<dim3(Dn, Bn * 3), 256>>>(x, Wih0, bhh);
    fused_kernel<<<Bn * 3 * 2 + Bn * Rn * 3, 512, smem_fused>>>(
        WihR, Whh, bih, bhh, emb, target, redW, redb, greenW, greenb,
        blueW, blueb, out);
}